// round 11
// baseline (speedup 1.0000x reference)
#include <cuda_runtime.h>

#define BATCH 8
#define NPTS  2048
#define KNN   16
#define TPB   256
#define NCB   (2 * BATCH)       // 16 (cloud,batch) groups
#define NCELL 512
#define NPAIR (NPTS / 2)        // 1024 pairs
#define QPB   64                // queries per block (4 threads each)
#define NTILE (NPTS / QPB)      // 32 blocks per group
#define NBLK  (NTILE * BATCH * 2)  // 512 knn blocks

__device__ unsigned long long g_sx[NCB * NPAIR];
__device__ unsigned long long g_sy[NCB * NPAIR];
__device__ unsigned long long g_sz[NCB * NPAIR];
__device__ float g_partials[NCB * NTILE];
__device__ int   g_count = 0;

// ---------------- f32x2 packed helpers ----------------
__device__ __forceinline__ unsigned long long x2add(unsigned long long a, unsigned long long b) {
    unsigned long long r; asm("add.rn.f32x2 %0, %1, %2;" : "=l"(r) : "l"(a), "l"(b)); return r;
}
__device__ __forceinline__ unsigned long long x2mul(unsigned long long a, unsigned long long b) {
    unsigned long long r; asm("mul.rn.f32x2 %0, %1, %2;" : "=l"(r) : "l"(a), "l"(b)); return r;
}
__device__ __forceinline__ unsigned long long x2fma(unsigned long long a, unsigned long long b,
                                                    unsigned long long c) {
    unsigned long long r; asm("fma.rn.f32x2 %0, %1, %2, %3;" : "=l"(r) : "l"(a), "l"(b), "l"(c)); return r;
}
__device__ __forceinline__ unsigned long long x2pack(float lo, float hi) {
    unsigned long long r; asm("mov.b64 %0, {%1, %2};" : "=l"(r) : "f"(lo), "f"(hi)); return r;
}
__device__ __forceinline__ void x2unpack(float& lo, float& hi, unsigned long long v) {
    asm("mov.b64 {%0, %1}, %2;" : "=f"(lo), "=f"(hi) : "l"(v));
}

__device__ __forceinline__ int spread3(int v) {
    return (v & 1) | ((v & 2) << 2) | ((v & 4) << 4);
}

// ---------------- counting sort by Morton cell ----------------
__global__ __launch_bounds__(512)
void cellsort_kernel(const float* __restrict__ seed, const float* __restrict__ gts) {
    __shared__ int hist[NCELL];
    __shared__ int wsum[16];
    __shared__ unsigned short cellOf[NPTS];

    const int b = blockIdx.x, c = blockIdx.y;
    const int tid = threadIdx.x;
    const int lane = tid & 31, wid = tid >> 5;
    const int g = c * BATCH + b;
    const float* __restrict__ src = (c == 0 ? seed : gts) + (size_t)b * NPTS * 3;

    hist[tid] = 0;
    __syncthreads();

    for (int p = tid; p < NPTS; p += 512) {
        const float x = src[3*p+0], y = src[3*p+1], z = src[3*p+2];
        int bx = (int)floorf((x + 3.0f) * (8.0f / 6.0f));
        int by = (int)floorf((y + 3.0f) * (8.0f / 6.0f));
        int bz = (int)floorf((z + 3.0f) * (8.0f / 6.0f));
        bx = min(max(bx, 0), 7); by = min(max(by, 0), 7); bz = min(max(bz, 0), 7);
        const int cell = spread3(bx) | (spread3(by) << 1) | (spread3(bz) << 2);
        cellOf[p] = (unsigned short)cell;
        atomicAdd(&hist[cell], 1);
    }
    __syncthreads();

    const int a = hist[tid];
    int s = a;
#pragma unroll
    for (int off = 1; off < 32; off <<= 1) {
        const int n = __shfl_up_sync(0xffffffffu, s, off);
        if (lane >= off) s += n;
    }
    if (lane == 31) wsum[wid] = s;
    __syncthreads();
    if (tid < 16) {
        int w = wsum[tid];
#pragma unroll
        for (int off = 1; off < 16; off <<= 1) {
            const int n = __shfl_up_sync(0xffffu, w, off, 16);
            if (tid >= off) w += n;
        }
        wsum[tid] = w;
    }
    __syncthreads();
    hist[tid] = (wid ? wsum[wid - 1] : 0) + s - a;
    __syncthreads();

    float* __restrict__ dx = (float*)(g_sx + g * NPAIR);
    float* __restrict__ dy = (float*)(g_sy + g * NPAIR);
    float* __restrict__ dz = (float*)(g_sz + g * NPAIR);
    for (int p = tid; p < NPTS; p += 512) {
        const float x = src[3*p+0], y = src[3*p+1], z = src[3*p+2];
        const int pos = atomicAdd(&hist[cellOf[p]], 1);
        dx[pos] = x; dy[pos] = y; dz[pos] = z;
    }
}

// depth-2 parallel sorted-ascending insert
#define INS(dv) do {                                                      \
    _Pragma("unroll")                                                     \
    for (int k = KNN - 1; k >= 1; --k)                                    \
        r[k] = fminf(r[k], fmaxf(r[k-1], (dv)));                          \
    r[0] = fminf(r[0], (dv));                                             \
} while (0)

#define DIST2(jp, dA, dB) {                                               \
    const unsigned long long X = sx[jp], Y = sy[jp], Z = sz[jp];          \
    const unsigned long long ddx = x2add(X, npx);                         \
    const unsigned long long ddy = x2add(Y, npy);                         \
    const unsigned long long ddz = x2add(Z, npz);                         \
    const unsigned long long d2 =                                         \
        x2fma(ddx, ddx, x2fma(ddy, ddy, x2mul(ddz, ddz)));                \
    x2unpack(dA, dB, d2);                                                 \
}

#define CE(i, j) { const float lo = fminf(v[i], v[j]);                    \
                   const float hi = fmaxf(v[i], v[j]);                    \
                   v[i] = lo; v[j] = hi; }

// ---------------- knn: 4 threads per query, sliced scan + shuffle merge ----------------
__global__ __launch_bounds__(TPB, 3)
void knn_kernel(float* __restrict__ out) {
    __shared__ unsigned long long sx[NPAIR];   // 8 KB each
    __shared__ unsigned long long sy[NPAIR];
    __shared__ unsigned long long sz[NPAIR];
    __shared__ float red[TPB / 32];
    __shared__ int   lastflag;

    const int tile = blockIdx.x, b = blockIdx.y, c = blockIdx.z;
    const int tid = threadIdx.x;
    const int lane = tid & 31, wid = tid >> 5;
    const int g = c * BATCH + b;
    const int slice = lane >> 3;              // 0..3
    const int qloc  = lane & 7;               // query within warp

    for (int j = tid; j < NPAIR; j += TPB) {
        sx[j] = g_sx[g * NPAIR + j];
        sy[j] = g_sy[g * NPAIR + j];
        sz[j] = g_sz[g * NPAIR + j];
    }
    __syncthreads();

    // query point: 8 queries per warp, 4 slices each
    const int q = tile * QPB + wid * 8 + qloc;
    float qx, qy, qz, hx, hy, hz;
    x2unpack(qx, hx, sx[q >> 1]);
    x2unpack(qy, hy, sy[q >> 1]);
    x2unpack(qz, hz, sz[q >> 1]);
    if (q & 1) { qx = hx; qy = hy; qz = hz; }
    const unsigned long long npx = x2pack(-qx, -qx);
    const unsigned long long npy = x2pack(-qy, -qy);
    const unsigned long long npz = x2pack(-qz, -qz);

    float r[KNN];
#pragma unroll
    for (int k = 0; k < KNN; k++) r[k] = 3.0e38f;

    // anchor = chunk containing this warp's queries (warp-uniform)
    const int anchor = (tile * (QPB / 2) + wid * 4) & ~15;
    const int sbase  = slice * 256 + slice;   // +slice stagger: distinct smem banks

    // phase A: first 16 pairs of own slice, ungated (slice 0 == query's own chunk)
#pragma unroll 4
    for (int i = 0; i < 16; ++i) {
        const int jp = (anchor + sbase + i) & (NPAIR - 1);
        float dA, dB; DIST2(jp, dA, dB);
        if (fminf(dA, dB) < r[KNN - 1]) { INS(dA); INS(dB); }
    }

    // gate: slice 0's r[15] is an upper bound on the global 16-NN distance
    const float cap = __shfl_sync(0xffffffffu, r[KNN - 1], qloc);

    // phase C: remaining 240 pairs, gated
#pragma unroll 4
    for (int i = 16; i < 256; ++i) {
        const int jp = (anchor + slice * 256 + ((i + slice) & 255)) & (NPAIR - 1);
        float dA, dB; DIST2(jp, dA, dB);
        const float m = fminf(dA, dB);
        if (m < r[KNN - 1] && m <= cap) { INS(dA); INS(dB); }
    }

    // level-1 merge (slices 0<->1, 2<->3): 16 smallest of union, then re-sort
    float v[KNN];
#pragma unroll
    for (int i = 0; i < KNN; ++i)
        v[i] = fminf(r[i], __shfl_xor_sync(0xffffffffu, r[KNN - 1 - i], 8));
    // bitonic cleanup -> ascending
    CE(0,8) CE(1,9) CE(2,10) CE(3,11) CE(4,12) CE(5,13) CE(6,14) CE(7,15)
    CE(0,4) CE(1,5) CE(2,6)  CE(3,7)  CE(8,12) CE(9,13) CE(10,14) CE(11,15)
    CE(0,2) CE(1,3) CE(4,6)  CE(5,7)  CE(8,10) CE(9,11) CE(12,14) CE(13,15)
    CE(0,1) CE(2,3) CE(4,5)  CE(6,7)  CE(8,9)  CE(10,11) CE(12,13) CE(14,15)

    // level-2 merge (pairs <->): 16 smallest of all 4 slices, sum directly
    float s16 = 0.0f;
#pragma unroll
    for (int i = 0; i < KNN; ++i)
        s16 += fminf(v[i], __shfl_xor_sync(0xffffffffu, v[KNN - 1 - i], 16));

    // warp sum: each query counted 4x (redundant groups) -> scale by 1/4 (exact)
#pragma unroll
    for (int off = 16; off > 0; off >>= 1)
        s16 += __shfl_down_sync(0xffffffffu, s16, off);
    if (lane == 0) red[wid] = s16 * 0.25f;
    __syncthreads();

    if (tid == 0) {
        float bs = 0.0f;
#pragma unroll
        for (int w = 0; w < TPB / 32; w++) bs += red[w];
        g_partials[g * NTILE + tile] = bs;
        __threadfence();
        const int t = atomicAdd(&g_count, 1);
        lastflag = (t == NBLK - 1);
    }
    __syncthreads();

    // fused finish
    if (lastflag) {
        __shared__ float ws[NCB];
        if (tid == 0) g_count = 0;
        {
            const int grp = tid >> 4, t16 = tid & 15;
            float vv = g_partials[grp * NTILE + t16] + g_partials[grp * NTILE + 16 + t16];
#pragma unroll
            for (int off = 8; off > 0; off >>= 1)
                vv += __shfl_down_sync(0xffffffffu, vv, off, 16);
            if (t16 == 0) ws[grp] = vv;
        }
        __syncthreads();
        if (tid == 0) {
            const double norm = 1.0 / ((double)NPTS * (double)KNN);
            double loss = 0.0;
            for (int gg = 0; gg < BATCH; ++gg) {
                const double diff = ((double)ws[gg] - (double)ws[BATCH + gg]) * norm;
                loss += diff * diff;
            }
            out[0] = (float)(loss / (double)BATCH);
        }
    }
}

extern "C" void kernel_launch(void* const* d_in, const int* in_sizes, int n_in,
                              void* d_out, int out_size) {
    const float* seed = (const float*)d_in[0];
    const float* gts  = (const float*)d_in[1];
    float* out = (float*)d_out;

    dim3 gsort(BATCH, 2);
    cellsort_kernel<<<gsort, 512>>>(seed, gts);

    dim3 gknn(NTILE, BATCH, 2);
    knn_kernel<<<gknn, TPB>>>(out);
}